// round 16
// baseline (speedup 1.0000x reference)
#include <cuda_runtime.h>
#include <cuda_fp16.h>
#include <stdint.h>
#include <math.h>

#define WIN 256
#define TTOT 5120   // 4096 doc tokens + 1024 summary tokens

// ---------------- scratch (device globals; no allocation allowed) -------------
__device__ float g_x[TTOT * 768];
__device__ float g_t[TTOT * 768];
__device__ float g_emb[16 * 768];
__device__ float g_bqkv[12 * 2304];
// fp16 activations
__device__ __half g_qkv[(size_t)TTOT * 2304];
__device__ __half g_xs[TTOT * 768];
__device__ __half g_as[TTOT * 768];
__device__ __half g_hs[(size_t)TTOT * 3072];
// fp16 weights: [K][N] per layer
__device__ __half g_wqkv[(size_t)12 * 768 * 2304];
__device__ __half g_wo[(size_t)12 * 768 * 768];
__device__ __half g_w1[(size_t)12 * 768 * 3072];
__device__ __half g_w2[(size_t)12 * 3072 * 768];

// GEMM smem: 3 stages of (A 128x72 + B 64x136) half, BK=64
#define GEMM_STAGES 3
#define GEMM_SMEM (GEMM_STAGES * (128 * 72 + 64 * 136) * 2)

// ---------------- merged weight conversion (Wo|W1|W2), 4 elems/thread ----------
#define WO_N 7077888ull     // 12*768*768
#define W1_N 28311552ull    // 12*768*3072
#define W2_N 28311552ull    // 12*3072*768

__global__ __launch_bounds__(256)
void conv_all_kernel(const float* __restrict__ Wo, const float* __restrict__ W1,
                     const float* __restrict__ W2, __half* __restrict__ wo,
                     __half* __restrict__ w1, __half* __restrict__ w2)
{
    size_t i = ((size_t)blockIdx.x * 256 + threadIdx.x) * 4;
    const float* src;
    __half* dst;
    if (i < WO_N) { src = Wo; dst = wo; }
    else if (i < WO_N + W1_N) { i -= WO_N; src = W1; dst = w1; }
    else { i -= WO_N + W1_N; src = W2; dst = w2; }
    const float4 v = *(const float4*)&src[i];
    *(__half2*)&dst[i]     = __floats2half2_rn(v.x, v.y);
    *(__half2*)&dst[i + 2] = __floats2half2_rn(v.z, v.w);
}

// ---------------- QKV pack + convert: Wq|Wk|Wv -> [768][2304] fp16, 4/thread ----
__global__ __launch_bounds__(256)
void conv_qkv_kernel(const float* __restrict__ Wq, const float* __restrict__ Wk,
                     const float* __restrict__ Wv, const float* __restrict__ bq,
                     const float* __restrict__ bk, const float* __restrict__ bv,
                     __half* __restrict__ W2h, float* __restrict__ bias)
{
    const int l = blockIdx.y;
    const int i = (blockIdx.x * 256 + threadIdx.x) * 4;   // < 768*2304, 4-aligned
    const int k = i / 2304, n = i % 2304;                 // 4-group never crosses 768-boundary
    const float* src = (n < 768) ? Wq : (n < 1536) ? Wk : Wv;
    const int nn = (n < 768) ? n : (n < 1536) ? n - 768 : n - 1536;
    const float4 v = *(const float4*)&src[((size_t)l * 768 + k) * 768 + nn];
    __half* O = W2h + (size_t)l * 768 * 2304 + i;
    *(__half2*)&O[0] = __floats2half2_rn(v.x, v.y);
    *(__half2*)&O[2] = __floats2half2_rn(v.z, v.w);
    if (i < 2304) {
        const float* bsrc = (i < 768) ? bq : (i < 1536) ? bk : bv;
        const int bn = (i < 768) ? i : (i < 1536) ? i - 768 : i - 1536;
        const float4 b4 = *(const float4*)&bsrc[(size_t)l * 768 + bn];
        *(float4*)&bias[l * 2304 + i] = b4;
    }
}

// ---------------- fp16 tensor-core GEMM, 128x128 tile, BK=64, 3-stage -----------
// C[M,N] = x~[M,K](fp16) @ W[K,N](fp16) + bias
// OUTMODE 0: fp32 out.  OUTMODE 1: gelu + fp16 out.  OUTMODE 2: fp16 out.
template <int OUTMODE>
__global__ __launch_bounds__(256, 2)
void gemm_fp16(const __half* __restrict__ A1, const __half* __restrict__ B1,
               const float* __restrict__ bias, void* __restrict__ Cout,
               int M, int N, int K)
{
    extern __shared__ __align__(16) unsigned char smem_raw[];
    __half* As = (__half*)smem_raw;                                  // [3][128][72]
    __half* Bs = (__half*)(smem_raw + GEMM_STAGES * 128 * 72 * 2);   // [3][64][136]

    const int tid  = threadIdx.x;
    const int lane = tid & 31, warp = tid >> 5;
    const int wm = warp >> 2, wn = warp & 3;
    const int row0 = blockIdx.y * 128, col0 = blockIdx.x * 128;
    const int nk = K >> 6;   // 64-wide k-chunks

    auto issue = [&](int kt) {
        const int stg = kt % GEMM_STAGES;
        const int kk = kt * 64;
        const unsigned aS = (unsigned)__cvta_generic_to_shared(As + stg * 128 * 72);
        const unsigned bS = (unsigned)__cvta_generic_to_shared(Bs + stg * 64 * 136);
#pragma unroll
        for (int j = 0; j < 4; j++) {
            const int ia = tid + j * 256;          // 0..1023
            const int ar = ia >> 3, ac8 = ia & 7;  // row 0..127, col-octet 0..7
            asm volatile("cp.async.cg.shared.global [%0], [%1], 16;"
                         :: "r"(aS + (unsigned)(ar * 72 + ac8 * 8) * 2u),
                            "l"(A1 + (size_t)(row0 + ar) * K + kk + ac8 * 8));
            const int br = ia >> 4, bc8 = ia & 15; // row 0..63, col-octet 0..15
            asm volatile("cp.async.cg.shared.global [%0], [%1], 16;"
                         :: "r"(bS + (unsigned)(br * 136 + bc8 * 8) * 2u),
                            "l"(B1 + (size_t)(kk + br) * N + col0 + bc8 * 8));
        }
        asm volatile("cp.async.commit_group;");
    };

    float acc[4][4][4];
#pragma unroll
    for (int mi = 0; mi < 4; mi++)
#pragma unroll
        for (int nj = 0; nj < 4; nj++)
#pragma unroll
            for (int q = 0; q < 4; q++) acc[mi][nj][q] = 0.f;

    issue(0);
    issue(1);

    for (int kt = 0; kt < nk; kt++) {
        asm volatile("cp.async.wait_group 1;");
        __syncthreads();
        if (kt + 2 < nk) issue(kt + 2);
        else asm volatile("cp.async.commit_group;");

        const int stg = kt % GEMM_STAGES;
        const unsigned aBase = (unsigned)__cvta_generic_to_shared(As + stg * 128 * 72);
        const unsigned bBase = (unsigned)__cvta_generic_to_shared(Bs + stg * 64 * 136);
#pragma unroll
        for (int ks = 0; ks < 4; ks++) {
            unsigned afrag[4][4];
            unsigned bfrag[4][2];
#pragma unroll
            for (int mi = 0; mi < 4; mi++) {
                const int r = wm * 64 + mi * 16 + (lane & 15);
                const int c = ks * 16 + (lane >> 4) * 8;
                const unsigned addr = aBase + (unsigned)(r * 72 + c) * 2u;
                asm volatile("ldmatrix.sync.aligned.m8n8.x4.shared.b16 {%0,%1,%2,%3}, [%4];"
                             : "=r"(afrag[mi][0]), "=r"(afrag[mi][1]),
                               "=r"(afrag[mi][2]), "=r"(afrag[mi][3])
                             : "r"(addr));
            }
#pragma unroll
            for (int njp = 0; njp < 2; njp++) {
                const int kr = ks * 16 + (lane & 15);
                const int c  = wn * 32 + njp * 16 + (lane >> 4) * 8;
                const unsigned addr = bBase + (unsigned)(kr * 136 + c) * 2u;
                asm volatile("ldmatrix.sync.aligned.m8n8.x4.trans.shared.b16 {%0,%1,%2,%3}, [%4];"
                             : "=r"(bfrag[2 * njp][0]), "=r"(bfrag[2 * njp][1]),
                               "=r"(bfrag[2 * njp + 1][0]), "=r"(bfrag[2 * njp + 1][1])
                             : "r"(addr));
            }
#pragma unroll
            for (int mi = 0; mi < 4; mi++)
#pragma unroll
                for (int nj = 0; nj < 4; nj++)
                    asm volatile("mma.sync.aligned.m16n8k16.row.col.f32.f16.f16.f32 "
                                 "{%0,%1,%2,%3}, {%4,%5,%6,%7}, {%8,%9}, {%0,%1,%2,%3};"
                                 : "+f"(acc[mi][nj][0]), "+f"(acc[mi][nj][1]),
                                   "+f"(acc[mi][nj][2]), "+f"(acc[mi][nj][3])
                                 : "r"(afrag[mi][0]), "r"(afrag[mi][1]),
                                   "r"(afrag[mi][2]), "r"(afrag[mi][3]),
                                   "r"(bfrag[nj][0]), "r"(bfrag[nj][1]));
        }
    }

#pragma unroll
    for (int mi = 0; mi < 4; mi++) {
        const int r = row0 + wm * 64 + mi * 16 + (lane >> 2);
#pragma unroll
        for (int nj = 0; nj < 4; nj++) {
            const int c = col0 + wn * 32 + nj * 8 + (lane & 3) * 2;
            const float2 b2 = *(const float2*)&bias[c];
            float o0 = acc[mi][nj][0] + b2.x;
            float o1 = acc[mi][nj][1] + b2.y;
            float o2 = acc[mi][nj][2] + b2.x;
            float o3 = acc[mi][nj][3] + b2.y;
            if (OUTMODE == 0) {
                float* C = (float*)Cout;
                *(float2*)&C[(size_t)r * N + c]       = make_float2(o0, o1);
                *(float2*)&C[(size_t)(r + 8) * N + c] = make_float2(o2, o3);
            } else {
                if (OUTMODE == 1) {
                    o0 = 0.5f * o0 * (1.f + erff(o0 * 0.70710678118654752f));
                    o1 = 0.5f * o1 * (1.f + erff(o1 * 0.70710678118654752f));
                    o2 = 0.5f * o2 * (1.f + erff(o2 * 0.70710678118654752f));
                    o3 = 0.5f * o3 * (1.f + erff(o3 * 0.70710678118654752f));
                }
                __half* C2 = (__half*)Cout;
                *(__half2*)&C2[(size_t)r * N + c]       = __floats2half2_rn(o0, o1);
                *(__half2*)&C2[(size_t)(r + 8) * N + c] = __floats2half2_rn(o2, o3);
            }
        }
    }
}

// ---------------- embedding + layernorm, merged batch, 192 thr, float4 ----------
__global__ __launch_bounds__(192)
void embed_ln_kernel(const int* __restrict__ doc_ids, const int* __restrict__ sum_ids,
                     const float* __restrict__ we,
                     const float* __restrict__ pe, const float* __restrict__ tt,
                     const float* __restrict__ g, const float* __restrict__ bta,
                     float* __restrict__ x, __half* __restrict__ xs)
{
    const int tok = blockIdx.x;
    const bool is_doc = tok < 4096;
    const int s  = is_doc ? (tok & 2047) : ((tok - 4096) & 511);
    const int id = is_doc ? doc_ids[tok] : sum_ids[tok - 4096];
    const int tid = threadIdx.x, lane = tid & 31, warp = tid >> 5;
    const int c0 = tid * 4;
    __shared__ float red[2][6];

    const float4 w4 = *(const float4*)&we[(size_t)id * 768 + c0];
    const float4 p4 = *(const float4*)&pe[(size_t)(s + 2) * 768 + c0];
    const float4 t4 = *(const float4*)&tt[c0];
    float4 v = make_float4(w4.x + p4.x + t4.x, w4.y + p4.y + t4.y,
                           w4.z + p4.z + t4.z, w4.w + p4.w + t4.w);

    float sum = v.x + v.y + v.z + v.w;
#pragma unroll
    for (int off = 16; off; off >>= 1) sum += __shfl_xor_sync(0xffffffffu, sum, off);
    if (lane == 0) red[0][warp] = sum;
    __syncthreads();
    const float mu = (red[0][0] + red[0][1] + red[0][2] + red[0][3] + red[0][4] + red[0][5]) * (1.f / 768.f);

    float vs = (v.x - mu) * (v.x - mu) + (v.y - mu) * (v.y - mu) +
               (v.z - mu) * (v.z - mu) + (v.w - mu) * (v.w - mu);
#pragma unroll
    for (int off = 16; off; off >>= 1) vs += __shfl_xor_sync(0xffffffffu, vs, off);
    if (lane == 0) red[1][warp] = vs;
    __syncthreads();
    const float rstd = rsqrtf((red[1][0] + red[1][1] + red[1][2] + red[1][3] + red[1][4] + red[1][5]) * (1.f / 768.f) + 1e-5f);

    const float4 g4 = *(const float4*)&g[c0];
    const float4 b4 = *(const float4*)&bta[c0];
    float4 o;
    o.x = (v.x - mu) * rstd * g4.x + b4.x;
    o.y = (v.y - mu) * rstd * g4.y + b4.y;
    o.z = (v.z - mu) * rstd * g4.z + b4.z;
    o.w = (v.w - mu) * rstd * g4.w + b4.w;
    *(float4*)&x[(size_t)tok * 768 + c0] = o;
    __half2* xo = (__half2*)&xs[(size_t)tok * 768 + c0];
    xo[0] = __floats2half2_rn(o.x, o.y);
    xo[1] = __floats2half2_rn(o.z, o.w);
}

// ---------------- x = LN(x + delta), 192 thr, float4 ----------------------------
__global__ __launch_bounds__(192)
void add_ln_kernel(float* __restrict__ x, const float* __restrict__ dlt,
                   const float* __restrict__ g, const float* __restrict__ bta,
                   __half* __restrict__ xs)
{
    const int tok = blockIdx.x;
    const int tid = threadIdx.x, lane = tid & 31, warp = tid >> 5;
    const int c0 = tid * 4;
    __shared__ float red[2][6];
    const size_t base = (size_t)tok * 768 + c0;

    const float4 x4 = *(const float4*)&x[base];
    const float4 d4 = *(const float4*)&dlt[base];
    float4 v = make_float4(x4.x + d4.x, x4.y + d4.y, x4.z + d4.z, x4.w + d4.w);

    float sum = v.x + v.y + v.z + v.w;
#pragma unroll
    for (int off = 16; off; off >>= 1) sum += __shfl_xor_sync(0xffffffffu, sum, off);
    if (lane == 0) red[0][warp] = sum;
    __syncthreads();
    const float mu = (red[0][0] + red[0][1] + red[0][2] + red[0][3] + red[0][4] + red[0][5]) * (1.f / 768.f);

    float vs = (v.x - mu) * (v.x - mu) + (v.y - mu) * (v.y - mu) +
               (v.z - mu) * (v.z - mu) + (v.w - mu) * (v.w - mu);
#pragma unroll
    for (int off = 16; off; off >>= 1) vs += __shfl_xor_sync(0xffffffffu, vs, off);
    if (lane == 0) red[1][warp] = vs;
    __syncthreads();
    const float rstd = rsqrtf((red[1][0] + red[1][1] + red[1][2] + red[1][3] + red[1][4] + red[1][5]) * (1.f / 768.f) + 1e-5f);

    const float4 g4 = *(const float4*)&g[c0];
    const float4 b4 = *(const float4*)&bta[c0];
    float4 o;
    o.x = (v.x - mu) * rstd * g4.x + b4.x;
    o.y = (v.y - mu) * rstd * g4.y + b4.y;
    o.z = (v.z - mu) * rstd * g4.z + b4.z;
    o.w = (v.w - mu) * rstd * g4.w + b4.w;
    *(float4*)&x[base] = o;
    __half2* xo = (__half2*)&xs[base];
    xo[0] = __floats2half2_rn(o.x, o.y);
    xo[1] = __floats2half2_rn(o.z, o.w);
}

// ---------------- sliding-window attention, doc+sum fused, 8 q/block ------------
// exp via ex2.approx.f16x2 (2 exps per MUFU op); weights stored fp16.
__global__ __launch_bounds__(256)
void attn_kernel(const __half* __restrict__ QKV, const int* __restrict__ doc_mask,
                 const int* __restrict__ sum_mask, __half* __restrict__ AS)
{
    const bool is_doc = blockIdx.x < 256;
    const int S = is_doc ? 2048 : 512;
    const int rowoff = is_doc ? 0 : 4096;
    const int* amask = is_doc ? doc_mask : sum_mask;
    const int q0 = (is_doc ? blockIdx.x : blockIdx.x - 256) * 8;
    const int b = blockIdx.y, h = blockIdx.z;
    const int tid = threadIdx.x, lane = tid & 31, warp = tid >> 5;
    const int g = lane >> 4, li = lane & 15;
    __shared__ float sc[8][528];
    __shared__ __half wsc[8][528];
    __shared__ float redm[16][8];
    __shared__ float reds[8][8];
    __shared__ float obuf[8][8][64];

    const size_t RS = 2304;
    const size_t base = ((size_t)rowoff + (size_t)b * S) * RS + (size_t)h * 64;
    const __half* Q  = QKV + base;
    const __half* Kp = QKV + base + 768;
    const __half* Vp = QKV + base + 1536;

    int j0 = q0 - WIN; if (j0 < 0) j0 = 0;
    int j1 = q0 + 7 + WIN; if (j1 > S - 1) j1 = S - 1;
    const int nk = j1 - j0 + 1;

    float4 q4[8];
#pragma unroll
    for (int qi = 0; qi < 8; qi++) {
        const __half2 a = *(const __half2*)&Q[(size_t)(q0 + qi) * RS + 4 * li];
        const __half2 bh = *(const __half2*)&Q[(size_t)(q0 + qi) * RS + 4 * li + 2];
        const float2 fa = __half22float2(a);
        const float2 fb = __half22float2(bh);
        q4[qi] = make_float4(fa.x, fa.y, fb.x, fb.y);
    }

    float lmax[8] = {-1e30f, -1e30f, -1e30f, -1e30f, -1e30f, -1e30f, -1e30f, -1e30f};
    for (int jj = warp * 2 + g; jj < nk; jj += 16) {
        const int j = j0 + jj;
        const __half2 ka = *(const __half2*)&Kp[(size_t)j * RS + 4 * li];
        const __half2 kb = *(const __half2*)&Kp[(size_t)j * RS + 4 * li + 2];
        const float2 fka = __half22float2(ka);
        const float2 fkb = __half22float2(kb);
        float p[8];
#pragma unroll
        for (int qi = 0; qi < 8; qi++)
            p[qi] = q4[qi].x * fka.x + q4[qi].y * fka.y + q4[qi].z * fkb.x + q4[qi].w * fkb.y;
#pragma unroll
        for (int off = 8; off; off >>= 1)
#pragma unroll
            for (int qi = 0; qi < 8; qi++)
                p[qi] += __shfl_xor_sync(0xffffffffu, p[qi], off);
        const int mok = amask[b * S + j];
#pragma unroll
        for (int qi = 0; qi < 8; qi++) {
            const int sq = q0 + qi;
            const bool valid = mok && (j >= sq - WIN) && (j <= sq + WIN);
            const float val = valid ? p[qi] * 0.125f : -1e9f;
            if (li == qi) sc[qi][jj] = val;
            lmax[qi] = fmaxf(lmax[qi], val);
        }
    }
    if (li == 0) {
#pragma unroll
        for (int qi = 0; qi < 8; qi++) redm[warp * 2 + g][qi] = lmax[qi];
    }
    __syncthreads();
    float mlog[8];
#pragma unroll
    for (int qi = 0; qi < 8; qi++) {
        float mm = redm[0][qi];
#pragma unroll
        for (int w = 1; w < 16; w++) mm = fmaxf(mm, redm[w][qi]);
        mlog[qi] = mm * 1.4426950408889634f;
    }

    // exp phase: half2 packed ex2 (2 exps / MUFU op), fp32 sums
    float lsum[8] = {0.f, 0.f, 0.f, 0.f, 0.f, 0.f, 0.f, 0.f};
    for (int jj = tid; jj < nk; jj += 256) {
#pragma unroll
        for (int qp = 0; qp < 4; qp++) {
            const float a0 = fmaf(sc[2 * qp][jj],     1.4426950408889634f, -mlog[2 * qp]);
            const float a1 = fmaf(sc[2 * qp + 1][jj], 1.4426950408889634f, -mlog[2 * qp + 1]);
            const __half2 hin = __floats2half2_rn(a0, a1);
            unsigned hr;
            asm volatile("ex2.approx.f16x2 %0, %1;" : "=r"(hr) : "r"(*(const unsigned*)&hin));
            const __half2 he = *(const __half2*)&hr;
            const float2 fe = __half22float2(he);
            lsum[2 * qp]     += fe.x;
            lsum[2 * qp + 1] += fe.y;
            wsc[2 * qp][jj]     = he.x;
            wsc[2 * qp + 1][jj] = he.y;
        }
    }
#pragma unroll
    for (int off = 16; off; off >>= 1)
#pragma unroll
        for (int qi = 0; qi < 8; qi++)
            lsum[qi] += __shfl_xor_sync(0xffffffffu, lsum[qi], off);
    if (lane == 0) {
#pragma unroll
        for (int qi = 0; qi < 8; qi++) reds[warp][qi] = lsum[qi];
    }
    __syncthreads();
    float inv[8];
#pragma unroll
    for (int qi = 0; qi < 8; qi++)
        inv[qi] = 1.f / (reds[0][qi] + reds[1][qi] + reds[2][qi] + reds[3][qi] +
                         reds[4][qi] + reds[5][qi] + reds[6][qi] + reds[7][qi]);

    float ax[8] = {0.f, 0.f, 0.f, 0.f, 0.f, 0.f, 0.f, 0.f};
    float ay[8] = {0.f, 0.f, 0.f, 0.f, 0.f, 0.f, 0.f, 0.f};
    for (int jj = warp; jj < nk; jj += 8) {
        const __half2 vh = *(const __half2*)&Vp[(size_t)(j0 + jj) * RS + 2 * lane];
        const float2 v2 = __half22float2(vh);
#pragma unroll
        for (int qi = 0; qi < 8; qi++) {
            const float p = __half2float(wsc[qi][jj]);
            ax[qi] += p * v2.x;
            ay[qi] += p * v2.y;
        }
    }
#pragma unroll
    for (int qi = 0; qi < 8; qi++) {
        obuf[warp][qi][2 * lane]     = ax[qi];
        obuf[warp][qi][2 * lane + 1] = ay[qi];
    }
    __syncthreads();

    {
        const int qi = warp;
        float vx = 0.f, vy = 0.f;
#pragma unroll
        for (int w = 0; w < 8; w++) {
            vx += obuf[w][qi][2 * lane];
            vy += obuf[w][qi][2 * lane + 1];
        }
        vx *= inv[qi];
        vy *= inv[qi];
        const size_t row = (size_t)rowoff + (size_t)b * S + q0 + qi;
        const int col = h * 64 + 2 * lane;
        *(__half2*)&AS[row * 768 + col] = __floats2half2_rn(vx, vy);
    }
}

// ---------------- span pooling ---------------------------------------------------
__global__ __launch_bounds__(256)
void span_pool_kernel(const float* __restrict__ seq, const float* __restrict__ masks,
                      const int* __restrict__ sidx, float* __restrict__ emb, int S)
{
    const int t = blockIdx.x;
    const int b = sidx[t];
    const int tid = threadIdx.x;
    float acc0 = 0.f, acc1 = 0.f, acc2 = 0.f, msum = 0.f;
    for (int s = 0; s < S; s++) {
        const float m = masks[(size_t)t * S + s];
        msum += m;
        const float* row = seq + (size_t)(b * S + s) * 768;
        acc0 += m * row[tid];
        acc1 += m * row[tid + 256];
        acc2 += m * row[tid + 512];
    }
    const float inv = 1.f / fmaxf(msum, 1e-9f);
    emb[(size_t)t * 768 + tid]       = acc0 * inv;
    emb[(size_t)t * 768 + tid + 256] = acc1 * inv;
    emb[(size_t)t * 768 + tid + 512] = acc2 * inv;
}

// ---------------- projection head ----------------------------------------------
__global__ __launch_bounds__(256)
void proj_kernel(const float* __restrict__ emb, const float* __restrict__ pW1,
                 const float* __restrict__ pb1, const float* __restrict__ pW2,
                 const float* __restrict__ pb2, float* __restrict__ out)
{
    const int t = blockIdx.x;
    const int tid = threadIdx.x;
    __shared__ float e[768];
    __shared__ float hdn[768];
    __shared__ float o[128];
    __shared__ float red[256];
    for (int d = tid; d < 768; d += 256) e[d] = emb[(size_t)t * 768 + d];
    __syncthreads();
    for (int j = tid; j < 768; j += 256) {
        float acc = pb1[j];
        for (int d = 0; d < 768; d++) acc += e[d] * pW1[(size_t)d * 768 + j];
        hdn[j] = fmaxf(acc, 0.f);
    }
    __syncthreads();
    if (tid < 128) {
        float acc = pb2[tid];
        for (int j = 0; j < 768; j++) acc += hdn[j] * pW2[(size_t)j * 128 + tid];
        o[tid] = acc;
    }
    __syncthreads();
    red[tid] = (tid < 128) ? o[tid] * o[tid] : 0.f;
    __syncthreads();
    for (int st = 128; st > 0; st >>= 1) { if (tid < st) red[tid] += red[tid + st]; __syncthreads(); }
    const float inv = 1.f / fmaxf(sqrtf(red[0]), 1e-12f);
    if (tid < 128) out[(size_t)t * 128 + tid] = o[tid] * inv;
}

// ---------------- driver ----------------------------------------------------------
extern "C" void kernel_launch(void* const* d_in, const int* in_sizes, int n_in,
                              void* d_out, int out_size)
{
    const int*   doc_ids   = (const int*)d_in[0];
    const int*   doc_mask  = (const int*)d_in[1];
    const int*   sum_ids   = (const int*)d_in[2];
    const int*   sum_mask  = (const int*)d_in[3];
    const float* og_masks  = (const float*)d_in[4];
    const float* llm_masks = (const float*)d_in[5];
    const int*   sidx      = (const int*)d_in[6];
    const float* word_emb  = (const float*)d_in[7];
    const float* pos_emb   = (const float*)d_in[8];
    const float* tt_emb    = (const float*)d_in[9];
    const float* ln_emb_g  = (const float*)d_in[10];
    const float* ln_emb_b  = (const float*)d_in[11];
    const float* Wq = (const float*)d_in[12];
    const float* bq = (const float*)d_in[13];
    const float* Wk = (const float*)d_in[14];
    const float* bk = (const float*)d_in[15];
    const float* Wv = (const float*)d_in[16];
    const float* bv = (const float*)d_in[17];
    const float* Wo = (const float*)d_in[18];
    const float* bo = (const float*)d_in[19];
    const float* ln1_g = (const float*)d_in[20];
    const float* ln1_b = (const float*)d_in[21];
    const float* W1 = (const float*)d_in[22];
    const float* b1 = (const float*)d_in[23];
    const float* W2 = (const float*)d_in[24];
    const float* b2 = (const float*)d_in[25];
    const float* ln2_g = (const float*)d_in[26];
    const float* ln2_b = (const float*)d_in[27];
    const float* pW1 = (const float*)d_in[28];
    const float* pb1 = (const float*)d_in[29];
    const float* pW2 = (const float*)d_in[30];
    const float* pb2 = (const float*)d_in[31];
    float* out = (float*)d_out;

    float *x, *tmp, *emb, *bqkv;
    __half *qkv, *xs, *as_, *hs, *wqkv, *wo, *w1, *w2;
    cudaGetSymbolAddress((void**)&x, g_x);
    cudaGetSymbolAddress((void**)&tmp, g_t);
    cudaGetSymbolAddress((void**)&emb, g_emb);
    cudaGetSymbolAddress((void**)&bqkv, g_bqkv);
    cudaGetSymbolAddress((void**)&qkv, g_qkv);
    cudaGetSymbolAddress((void**)&xs, g_xs);
    cudaGetSymbolAddress((void**)&as_, g_as);
    cudaGetSymbolAddress((void**)&hs, g_hs);
    cudaGetSymbolAddress((void**)&wqkv, g_wqkv);
    cudaGetSymbolAddress((void**)&wo, g_wo);
    cudaGetSymbolAddress((void**)&w1, g_w1);
    cudaGetSymbolAddress((void**)&w2, g_w2);

    cudaFuncSetAttribute(gemm_fp16<0>, cudaFuncAttributeMaxDynamicSharedMemorySize, GEMM_SMEM);
    cudaFuncSetAttribute(gemm_fp16<1>, cudaFuncAttributeMaxDynamicSharedMemorySize, GEMM_SMEM);
    cudaFuncSetAttribute(gemm_fp16<2>, cudaFuncAttributeMaxDynamicSharedMemorySize, GEMM_SMEM);

    // one-time (per launch) weight conversion to fp16 layouts (2 launches)
    conv_qkv_kernel<<<dim3(1728, 12), 256>>>(Wq, Wk, Wv, bq, bk, bv, wqkv, bqkv);
    conv_all_kernel<<<62208, 256>>>(Wo, W1, W2, wo, w1, w2);

    // merged encoder: rows [0,4096) = doc (B=2,S=2048), rows [4096,5120) = summary
    const int T = TTOT;
    embed_ln_kernel<<<T, 192>>>(doc_ids, sum_ids, word_emb, pos_emb, tt_emb,
                                ln_emb_g, ln_emb_b, x, xs);
    for (int l = 0; l < 12; l++) {
        dim3 g768(6, T / 128), g2304(18, T / 128), g3072(24, T / 128);
        gemm_fp16<2><<<g2304, 256, GEMM_SMEM>>>(xs, wqkv + (size_t)l * 768 * 2304,
                                                bqkv + l * 2304, qkv, T, 2304, 768);
        attn_kernel<<<dim3(320, 2, 12), 256>>>(qkv, doc_mask, sum_mask, as_);
        gemm_fp16<0><<<g768, 256, GEMM_SMEM>>>(as_, wo + (size_t)l * 768 * 768,
                                               bo + l * 768, tmp, T, 768, 768);
        add_ln_kernel<<<T, 192>>>(x, tmp, ln1_g + l * 768, ln1_b + l * 768, xs);
        gemm_fp16<1><<<g3072, 256, GEMM_SMEM>>>(xs, w1 + (size_t)l * 768 * 3072,
                                                b1 + l * 3072, hs, T, 3072, 768);
        gemm_fp16<0><<<g768, 256, GEMM_SMEM>>>(hs, w2 + (size_t)l * 3072 * 768,
                                               b2 + l * 768, tmp, T, 768, 3072);
        add_ln_kernel<<<T, 192>>>(x, tmp, ln2_g + l * 768, ln2_b + l * 768, xs);
    }

    // span pooling + projection heads
    span_pool_kernel<<<16, 256>>>(x, og_masks, sidx, emb, 2048);
    proj_kernel<<<16, 256>>>(emb, pW1, pb1, pW2, pb2, out);
    span_pool_kernel<<<16, 256>>>(x + (size_t)4096 * 768, llm_masks, sidx, emb, 512);
    proj_kernel<<<16, 256>>>(emb, pW1, pb1, pW2, pb2, out + 16 * 128);
}

// round 17
// speedup vs baseline: 2.0664x; 2.0664x over previous
#include <cuda_runtime.h>
#include <cuda_fp16.h>
#include <stdint.h>
#include <math.h>

#define WIN 256
#define TTOT 5120   // 4096 doc tokens + 1024 summary tokens

// ---------------- scratch (device globals; no allocation allowed) -------------
__device__ float g_x[TTOT * 768];
__device__ float g_t[TTOT * 768];
__device__ float g_emb[16 * 768];
__device__ float g_bqkv[12 * 2304];
// fp16 activations
__device__ __half g_qkv[(size_t)TTOT * 2304];
__device__ __half g_xs[TTOT * 768];
__device__ __half g_as[TTOT * 768];
__device__ __half g_hs[(size_t)TTOT * 3072];
// fp16 weights: [K][N] per layer
__device__ __half g_wqkv[(size_t)12 * 768 * 2304];
__device__ __half g_wo[(size_t)12 * 768 * 768];
__device__ __half g_w1[(size_t)12 * 768 * 3072];
__device__ __half g_w2[(size_t)12 * 3072 * 768];

// GEMM smem: 3 stages of (A 128x72 + B 64x136) half, BK=64
#define GEMM_STAGES 3
#define GEMM_SMEM (GEMM_STAGES * (128 * 72 + 64 * 136) * 2)

// attention smem plan (dynamic)
#define AT_QS   0          // 16x72 half        = 2304 B
#define AT_KV   2304       // 3x64x72 half      = 27648 B
#define AT_SC   29952      // 16x584 half       = 18688 B
#define AT_MSK  48640      // 576 int           = 2304 B
#define AT_RINV 50944      // 16 float          = 64 B
#define ATTN_SMEM 51008

// ---------------- merged weight conversion (Wo|W1|W2), 4 elems/thread ----------
#define WO_N 7077888ull     // 12*768*768
#define W1_N 28311552ull    // 12*768*3072
#define W2_N 28311552ull    // 12*3072*768

__global__ __launch_bounds__(256)
void conv_all_kernel(const float* __restrict__ Wo, const float* __restrict__ W1,
                     const float* __restrict__ W2, __half* __restrict__ wo,
                     __half* __restrict__ w1, __half* __restrict__ w2)
{
    size_t i = ((size_t)blockIdx.x * 256 + threadIdx.x) * 4;
    const float* src;
    __half* dst;
    if (i < WO_N) { src = Wo; dst = wo; }
    else if (i < WO_N + W1_N) { i -= WO_N; src = W1; dst = w1; }
    else { i -= WO_N + W1_N; src = W2; dst = w2; }
    const float4 v = *(const float4*)&src[i];
    *(__half2*)&dst[i]     = __floats2half2_rn(v.x, v.y);
    *(__half2*)&dst[i + 2] = __floats2half2_rn(v.z, v.w);
}

// ---------------- QKV pack + convert: Wq|Wk|Wv -> [768][2304] fp16, 4/thread ----
__global__ __launch_bounds__(256)
void conv_qkv_kernel(const float* __restrict__ Wq, const float* __restrict__ Wk,
                     const float* __restrict__ Wv, const float* __restrict__ bq,
                     const float* __restrict__ bk, const float* __restrict__ bv,
                     __half* __restrict__ W2h, float* __restrict__ bias)
{
    const int l = blockIdx.y;
    const int i = (blockIdx.x * 256 + threadIdx.x) * 4;   // < 768*2304, 4-aligned
    const int k = i / 2304, n = i % 2304;                 // 4-group never crosses 768-boundary
    const float* src = (n < 768) ? Wq : (n < 1536) ? Wk : Wv;
    const int nn = (n < 768) ? n : (n < 1536) ? n - 768 : n - 1536;
    const float4 v = *(const float4*)&src[((size_t)l * 768 + k) * 768 + nn];
    __half* O = W2h + (size_t)l * 768 * 2304 + i;
    *(__half2*)&O[0] = __floats2half2_rn(v.x, v.y);
    *(__half2*)&O[2] = __floats2half2_rn(v.z, v.w);
    if (i < 2304) {
        const float* bsrc = (i < 768) ? bq : (i < 1536) ? bk : bv;
        const int bn = (i < 768) ? i : (i < 1536) ? i - 768 : i - 1536;
        const float4 b4 = *(const float4*)&bsrc[(size_t)l * 768 + bn];
        *(float4*)&bias[l * 2304 + i] = b4;
    }
}

// ---------------- fp16 tensor-core GEMM, 128x128 tile, BK=64, 3-stage -----------
template <int OUTMODE>
__global__ __launch_bounds__(256, 2)
void gemm_fp16(const __half* __restrict__ A1, const __half* __restrict__ B1,
               const float* __restrict__ bias, void* __restrict__ Cout,
               int M, int N, int K)
{
    extern __shared__ __align__(16) unsigned char smem_raw[];
    __half* As = (__half*)smem_raw;                                  // [3][128][72]
    __half* Bs = (__half*)(smem_raw + GEMM_STAGES * 128 * 72 * 2);   // [3][64][136]

    const int tid  = threadIdx.x;
    const int lane = tid & 31, warp = tid >> 5;
    const int wm = warp >> 2, wn = warp & 3;
    const int row0 = blockIdx.y * 128, col0 = blockIdx.x * 128;
    const int nk = K >> 6;   // 64-wide k-chunks

    auto issue = [&](int kt) {
        const int stg = kt % GEMM_STAGES;
        const int kk = kt * 64;
        const unsigned aS = (unsigned)__cvta_generic_to_shared(As + stg * 128 * 72);
        const unsigned bS = (unsigned)__cvta_generic_to_shared(Bs + stg * 64 * 136);
#pragma unroll
        for (int j = 0; j < 4; j++) {
            const int ia = tid + j * 256;          // 0..1023
            const int ar = ia >> 3, ac8 = ia & 7;  // row 0..127, col-octet 0..7
            asm volatile("cp.async.cg.shared.global [%0], [%1], 16;"
                         :: "r"(aS + (unsigned)(ar * 72 + ac8 * 8) * 2u),
                            "l"(A1 + (size_t)(row0 + ar) * K + kk + ac8 * 8));
            const int br = ia >> 4, bc8 = ia & 15; // row 0..63, col-octet 0..15
            asm volatile("cp.async.cg.shared.global [%0], [%1], 16;"
                         :: "r"(bS + (unsigned)(br * 136 + bc8 * 8) * 2u),
                            "l"(B1 + (size_t)(kk + br) * N + col0 + bc8 * 8));
        }
        asm volatile("cp.async.commit_group;");
    };

    float acc[4][4][4];
#pragma unroll
    for (int mi = 0; mi < 4; mi++)
#pragma unroll
        for (int nj = 0; nj < 4; nj++)
#pragma unroll
            for (int q = 0; q < 4; q++) acc[mi][nj][q] = 0.f;

    issue(0);
    issue(1);

    for (int kt = 0; kt < nk; kt++) {
        asm volatile("cp.async.wait_group 1;");
        __syncthreads();
        if (kt + 2 < nk) issue(kt + 2);
        else asm volatile("cp.async.commit_group;");

        const int stg = kt % GEMM_STAGES;
        const unsigned aBase = (unsigned)__cvta_generic_to_shared(As + stg * 128 * 72);
        const unsigned bBase = (unsigned)__cvta_generic_to_shared(Bs + stg * 64 * 136);
#pragma unroll
        for (int ks = 0; ks < 4; ks++) {
            unsigned afrag[4][4];
            unsigned bfrag[4][2];
#pragma unroll
            for (int mi = 0; mi < 4; mi++) {
                const int r = wm * 64 + mi * 16 + (lane & 15);
                const int c = ks * 16 + (lane >> 4) * 8;
                const unsigned addr = aBase + (unsigned)(r * 72 + c) * 2u;
                asm volatile("ldmatrix.sync.aligned.m8n8.x4.shared.b16 {%0,%1,%2,%3}, [%4];"
                             : "=r"(afrag[mi][0]), "=r"(afrag[mi][1]),
                               "=r"(afrag[mi][2]), "=r"(afrag[mi][3])
                             : "r"(addr));
            }
#pragma unroll
            for (int njp = 0; njp < 2; njp++) {
                const int kr = ks * 16 + (lane & 15);
                const int c  = wn * 32 + njp * 16 + (lane >> 4) * 8;
                const unsigned addr = bBase + (unsigned)(kr * 136 + c) * 2u;
                asm volatile("ldmatrix.sync.aligned.m8n8.x4.trans.shared.b16 {%0,%1,%2,%3}, [%4];"
                             : "=r"(bfrag[2 * njp][0]), "=r"(bfrag[2 * njp][1]),
                               "=r"(bfrag[2 * njp + 1][0]), "=r"(bfrag[2 * njp + 1][1])
                             : "r"(addr));
            }
#pragma unroll
            for (int mi = 0; mi < 4; mi++)
#pragma unroll
                for (int nj = 0; nj < 4; nj++)
                    asm volatile("mma.sync.aligned.m16n8k16.row.col.f32.f16.f16.f32 "
                                 "{%0,%1,%2,%3}, {%4,%5,%6,%7}, {%8,%9}, {%0,%1,%2,%3};"
                                 : "+f"(acc[mi][nj][0]), "+f"(acc[mi][nj][1]),
                                   "+f"(acc[mi][nj][2]), "+f"(acc[mi][nj][3])
                                 : "r"(afrag[mi][0]), "r"(afrag[mi][1]),
                                   "r"(afrag[mi][2]), "r"(afrag[mi][3]),
                                   "r"(bfrag[nj][0]), "r"(bfrag[nj][1]));
        }
    }

#pragma unroll
    for (int mi = 0; mi < 4; mi++) {
        const int r = row0 + wm * 64 + mi * 16 + (lane >> 2);
#pragma unroll
        for (int nj = 0; nj < 4; nj++) {
            const int c = col0 + wn * 32 + nj * 8 + (lane & 3) * 2;
            const float2 b2 = *(const float2*)&bias[c];
            float o0 = acc[mi][nj][0] + b2.x;
            float o1 = acc[mi][nj][1] + b2.y;
            float o2 = acc[mi][nj][2] + b2.x;
            float o3 = acc[mi][nj][3] + b2.y;
            if (OUTMODE == 0) {
                float* C = (float*)Cout;
                *(float2*)&C[(size_t)r * N + c]       = make_float2(o0, o1);
                *(float2*)&C[(size_t)(r + 8) * N + c] = make_float2(o2, o3);
            } else {
                if (OUTMODE == 1) {
                    o0 = 0.5f * o0 * (1.f + erff(o0 * 0.70710678118654752f));
                    o1 = 0.5f * o1 * (1.f + erff(o1 * 0.70710678118654752f));
                    o2 = 0.5f * o2 * (1.f + erff(o2 * 0.70710678118654752f));
                    o3 = 0.5f * o3 * (1.f + erff(o3 * 0.70710678118654752f));
                }
                __half* C2 = (__half*)Cout;
                *(__half2*)&C2[(size_t)r * N + c]       = __floats2half2_rn(o0, o1);
                *(__half2*)&C2[(size_t)(r + 8) * N + c] = __floats2half2_rn(o2, o3);
            }
        }
    }
}

// ---------------- embedding + layernorm, merged batch, 192 thr, float4 ----------
__global__ __launch_bounds__(192)
void embed_ln_kernel(const int* __restrict__ doc_ids, const int* __restrict__ sum_ids,
                     const float* __restrict__ we,
                     const float* __restrict__ pe, const float* __restrict__ tt,
                     const float* __restrict__ g, const float* __restrict__ bta,
                     float* __restrict__ x, __half* __restrict__ xs)
{
    const int tok = blockIdx.x;
    const bool is_doc = tok < 4096;
    const int s  = is_doc ? (tok & 2047) : ((tok - 4096) & 511);
    const int id = is_doc ? doc_ids[tok] : sum_ids[tok - 4096];
    const int tid = threadIdx.x, lane = tid & 31, warp = tid >> 5;
    const int c0 = tid * 4;
    __shared__ float red[2][6];

    const float4 w4 = *(const float4*)&we[(size_t)id * 768 + c0];
    const float4 p4 = *(const float4*)&pe[(size_t)(s + 2) * 768 + c0];
    const float4 t4 = *(const float4*)&tt[c0];
    float4 v = make_float4(w4.x + p4.x + t4.x, w4.y + p4.y + t4.y,
                           w4.z + p4.z + t4.z, w4.w + p4.w + t4.w);

    float sum = v.x + v.y + v.z + v.w;
#pragma unroll
    for (int off = 16; off; off >>= 1) sum += __shfl_xor_sync(0xffffffffu, sum, off);
    if (lane == 0) red[0][warp] = sum;
    __syncthreads();
    const float mu = (red[0][0] + red[0][1] + red[0][2] + red[0][3] + red[0][4] + red[0][5]) * (1.f / 768.f);

    float vs = (v.x - mu) * (v.x - mu) + (v.y - mu) * (v.y - mu) +
               (v.z - mu) * (v.z - mu) + (v.w - mu) * (v.w - mu);
#pragma unroll
    for (int off = 16; off; off >>= 1) vs += __shfl_xor_sync(0xffffffffu, vs, off);
    if (lane == 0) red[1][warp] = vs;
    __syncthreads();
    const float rstd = rsqrtf((red[1][0] + red[1][1] + red[1][2] + red[1][3] + red[1][4] + red[1][5]) * (1.f / 768.f) + 1e-5f);

    const float4 g4 = *(const float4*)&g[c0];
    const float4 b4 = *(const float4*)&bta[c0];
    float4 o;
    o.x = (v.x - mu) * rstd * g4.x + b4.x;
    o.y = (v.y - mu) * rstd * g4.y + b4.y;
    o.z = (v.z - mu) * rstd * g4.z + b4.z;
    o.w = (v.w - mu) * rstd * g4.w + b4.w;
    *(float4*)&x[(size_t)tok * 768 + c0] = o;
    __half2* xo = (__half2*)&xs[(size_t)tok * 768 + c0];
    xo[0] = __floats2half2_rn(o.x, o.y);
    xo[1] = __floats2half2_rn(o.z, o.w);
}

// ---------------- x = LN(x + delta), 192 thr, float4 ----------------------------
__global__ __launch_bounds__(192)
void add_ln_kernel(float* __restrict__ x, const float* __restrict__ dlt,
                   const float* __restrict__ g, const float* __restrict__ bta,
                   __half* __restrict__ xs)
{
    const int tok = blockIdx.x;
    const int tid = threadIdx.x, lane = tid & 31, warp = tid >> 5;
    const int c0 = tid * 4;
    __shared__ float red[2][6];
    const size_t base = (size_t)tok * 768 + c0;

    const float4 x4 = *(const float4*)&x[base];
    const float4 d4 = *(const float4*)&dlt[base];
    float4 v = make_float4(x4.x + d4.x, x4.y + d4.y, x4.z + d4.z, x4.w + d4.w);

    float sum = v.x + v.y + v.z + v.w;
#pragma unroll
    for (int off = 16; off; off >>= 1) sum += __shfl_xor_sync(0xffffffffu, sum, off);
    if (lane == 0) red[0][warp] = sum;
    __syncthreads();
    const float mu = (red[0][0] + red[0][1] + red[0][2] + red[0][3] + red[0][4] + red[0][5]) * (1.f / 768.f);

    float vs = (v.x - mu) * (v.x - mu) + (v.y - mu) * (v.y - mu) +
               (v.z - mu) * (v.z - mu) + (v.w - mu) * (v.w - mu);
#pragma unroll
    for (int off = 16; off; off >>= 1) vs += __shfl_xor_sync(0xffffffffu, vs, off);
    if (lane == 0) red[1][warp] = vs;
    __syncthreads();
    const float rstd = rsqrtf((red[1][0] + red[1][1] + red[1][2] + red[1][3] + red[1][4] + red[1][5]) * (1.f / 768.f) + 1e-5f);

    const float4 g4 = *(const float4*)&g[c0];
    const float4 b4 = *(const float4*)&bta[c0];
    float4 o;
    o.x = (v.x - mu) * rstd * g4.x + b4.x;
    o.y = (v.y - mu) * rstd * g4.y + b4.y;
    o.z = (v.z - mu) * rstd * g4.z + b4.z;
    o.w = (v.w - mu) * rstd * g4.w + b4.w;
    *(float4*)&x[base] = o;
    __half2* xo = (__half2*)&xs[base];
    xo[0] = __floats2half2_rn(o.x, o.y);
    xo[1] = __floats2half2_rn(o.z, o.w);
}

// ---------------- tensor-core sliding-window attention --------------------------
// Block = 16 queries of one (seqset, b, h). 128 thr / 4 warps.
// Key frame: 576 slots [q0-256, q0+319]; chunks of 64; 0-8 = K, 9-17 = V.
__global__ __launch_bounds__(128)
void attn_kernel(const __half* __restrict__ QKV, const int* __restrict__ doc_mask,
                 const int* __restrict__ sum_mask, __half* __restrict__ AS)
{
    extern __shared__ __align__(16) unsigned char smem[];
    __half* qs  = (__half*)(smem + AT_QS);    // [16][72]
    __half* kvp = (__half*)(smem + AT_KV);    // [3][64][72]
    __half* sc  = (__half*)(smem + AT_SC);    // [16][584]
    int*    msk = (int*)(smem + AT_MSK);      // [576]
    float*  rinv = (float*)(smem + AT_RINV);  // [16]

    const bool is_doc = blockIdx.x < 128;
    const int S = is_doc ? 2048 : 512;
    const int rowoff = is_doc ? 0 : 4096;
    const int* amask = is_doc ? doc_mask : sum_mask;
    const int q0 = (is_doc ? blockIdx.x : blockIdx.x - 128) * 16;
    const int b = blockIdx.y, h = blockIdx.z;
    const int tid = threadIdx.x, lane = tid & 31, warp = tid >> 5;

    const size_t RS = 2304;
    const size_t gbase = ((size_t)rowoff + (size_t)b * S) * RS + (size_t)h * 64;
    const __half* Qg = QKV + gbase;
    const __half* Kg = QKV + gbase + 768;
    const __half* Vg = QKV + gbase + 1536;
    const int j0 = q0 - WIN;

    // mask smem (also encodes 0<=j<S)
    for (int s_ = tid; s_ < 576; s_ += 128) {
        const int j = j0 + s_;
        msk[s_] = (j >= 0 && j < S) ? amask[b * S + j] : 0;
    }

    // Q tile cp.async: 16 rows x 128B (joins group 0)
    {
        const int r = tid >> 3, c8 = (tid & 7) * 8;
        const unsigned qaddr = (unsigned)__cvta_generic_to_shared(qs + r * 72 + c8);
        asm volatile("cp.async.cg.shared.global [%0], [%1], 16;"
                     :: "r"(qaddr), "l"(Qg + (size_t)(q0 + r) * RS + c8));
    }

    auto issue = [&](int cc) {
        const int buf = cc % 3;
        const bool isK = cc < 9;
        const int c = isK ? cc : cc - 9;
        const __half* src = isK ? Kg : Vg;
        __half* dstb = kvp + buf * (64 * 72);
#pragma unroll
        for (int t = 0; t < 4; t++) {
            const int ia = tid + t * 128;          // 0..511
            const int r = ia >> 3, c8 = (ia & 7) * 8;
            int j = j0 + c * 64 + r;
            j = j < 0 ? 0 : (j >= S ? S - 1 : j);  // clamped (garbage masked later)
            const unsigned a = (unsigned)__cvta_generic_to_shared(dstb + r * 72 + c8);
            asm volatile("cp.async.cg.shared.global [%0], [%1], 16;"
                         :: "r"(a), "l"(src + (size_t)j * RS + c8));
        }
        asm volatile("cp.async.commit_group;");
    };

    issue(0);
    issue(1);

    unsigned qfrag[4][4];
    float pacc[2][4];
#pragma unroll
    for (int t = 0; t < 2; t++)
#pragma unroll
        for (int q = 0; q < 4; q++) pacc[t][q] = 0.f;

    const int row = lane >> 2, colp = 2 * (lane & 3);

    for (int cc = 0; cc < 18; cc++) {
        asm volatile("cp.async.wait_group 1;");
        __syncthreads();
        if (cc + 2 < 18) issue(cc + 2);
        else asm volatile("cp.async.commit_group;");
        const unsigned kvB = (unsigned)__cvta_generic_to_shared(kvp + (cc % 3) * (64 * 72));

        if (cc == 0) {
            const unsigned qB = (unsigned)__cvta_generic_to_shared(qs);
#pragma unroll
            for (int ks = 0; ks < 4; ks++) {
                const unsigned addr = qB + (unsigned)((lane & 15) * 72 + ks * 16 + (lane >> 4) * 8) * 2u;
                asm volatile("ldmatrix.sync.aligned.m8n8.x4.shared.b16 {%0,%1,%2,%3}, [%4];"
                             : "=r"(qfrag[ks][0]), "=r"(qfrag[ks][1]),
                               "=r"(qfrag[ks][2]), "=r"(qfrag[ks][3])
                             : "r"(addr));
            }
        }

        if (cc < 9) {
            // QK^T for 64 keys: warp handles n-tiles 2w, 2w+1
#pragma unroll
            for (int dt = 0; dt < 2; dt++) {
                const int nt = warp * 2 + dt;
                float acc[4] = {0.f, 0.f, 0.f, 0.f};
#pragma unroll
                for (int ks = 0; ks < 4; ks++) {
                    unsigned bfr[2];
                    const unsigned addr = kvB + (unsigned)((nt * 8 + (lane & 7)) * 72 +
                                                           ks * 16 + ((lane >> 3) & 1) * 8) * 2u;
                    asm volatile("ldmatrix.sync.aligned.m8n8.x2.shared.b16 {%0,%1}, [%2];"
                                 : "=r"(bfr[0]), "=r"(bfr[1]) : "r"(addr));
                    asm volatile("mma.sync.aligned.m16n8k16.row.col.f32.f16.f16.f32 "
                                 "{%0,%1,%2,%3}, {%4,%5,%6,%7}, {%8,%9}, {%0,%1,%2,%3};"
                                 : "+f"(acc[0]), "+f"(acc[1]), "+f"(acc[2]), "+f"(acc[3])
                                 : "r"(qfrag[ks][0]), "r"(qfrag[ks][1]),
                                   "r"(qfrag[ks][2]), "r"(qfrag[ks][3]),
                                   "r"(bfr[0]), "r"(bfr[1]));
                }
                const int slot = cc * 64 + nt * 8 + colp;
                const int m0 = msk[slot], m1 = msk[slot + 1];
                const float v00 = (m0 && slot     >= row     && slot     <= row + 512)     ? acc[0] * 0.125f : -60000.f;
                const float v01 = (m1 && slot + 1 >= row     && slot + 1 <= row + 512)     ? acc[1] * 0.125f : -60000.f;
                const float v10 = (m0 && slot     >= row + 8 && slot     <= row + 8 + 512) ? acc[2] * 0.125f : -60000.f;
                const float v11 = (m1 && slot + 1 >= row + 8 && slot + 1 <= row + 8 + 512) ? acc[3] * 0.125f : -60000.f;
                *(__half2*)&sc[row * 584 + slot]       = __floats2half2_rn(v00, v01);
                *(__half2*)&sc[(row + 8) * 584 + slot] = __floats2half2_rn(v10, v11);
            }
        } else {
            if (cc == 9) {
                // softmax: 8 threads per row, contiguous 72-slot segments
                const int r = tid >> 3, seg = tid & 7;
                __half* rp = sc + r * 584 + seg * 72;
                float mx = -1e30f;
#pragma unroll 4
                for (int i = 0; i < 36; i++) {
                    const float2 f = __half22float2(*(const __half2*)&rp[2 * i]);
                    mx = fmaxf(mx, fmaxf(f.x, f.y));
                }
#pragma unroll
                for (int off = 4; off; off >>= 1) mx = fmaxf(mx, __shfl_xor_sync(0xffffffffu, mx, off));
                const float ml = mx * 1.4426950408889634f;
                float sm = 0.f;
#pragma unroll 4
                for (int i = 0; i < 36; i++) {
                    const float2 f = __half22float2(*(const __half2*)&rp[2 * i]);
                    const float a0 = fmaf(f.x, 1.4426950408889634f, -ml);
                    const float a1 = fmaf(f.y, 1.4426950408889634f, -ml);
                    const __half2 hin = __floats2half2_rn(a0, a1);
                    unsigned hr;
                    asm volatile("ex2.approx.f16x2 %0, %1;" : "=r"(hr) : "r"(*(const unsigned*)&hin));
                    const float2 fe = __half22float2(*(const __half2*)&hr);
                    sm += fe.x + fe.y;
                    *(__half2*)&rp[2 * i] = *(const __half2*)&hr;
                }
#pragma unroll
                for (int off = 4; off; off >>= 1) sm += __shfl_xor_sync(0xffffffffu, sm, off);
                if (seg == 0) rinv[r] = 1.f / sm;
                __syncthreads();
            }
            // PV chunk cv = cc - 9: warp handles dims [w*16, w*16+16)
            const int cv = cc - 9;
            const unsigned scB = (unsigned)__cvta_generic_to_shared(sc);
#pragma unroll
            for (int ks = 0; ks < 4; ks++) {
                unsigned afr[4];
                const unsigned aaddr = scB + (unsigned)((lane & 15) * 584 +
                                                        (cv * 4 + ks) * 16 + (lane >> 4) * 8) * 2u;
                asm volatile("ldmatrix.sync.aligned.m8n8.x4.shared.b16 {%0,%1,%2,%3}, [%4];"
                             : "=r"(afr[0]), "=r"(afr[1]), "=r"(afr[2]), "=r"(afr[3])
                             : "r"(aaddr));
#pragma unroll
                for (int dt = 0; dt < 2; dt++) {
                    unsigned bfr[2];
                    const unsigned baddr = kvB + (unsigned)((ks * 16 + (lane & 15)) * 72 +
                                                            warp * 16 + dt * 8) * 2u;
                    asm volatile("ldmatrix.sync.aligned.m8n8.x2.trans.shared.b16 {%0,%1}, [%2];"
                                 : "=r"(bfr[0]), "=r"(bfr[1]) : "r"(baddr));
                    asm volatile("mma.sync.aligned.m16n8k16.row.col.f32.f16.f16.f32 "
                                 "{%0,%1,%2,%3}, {%4,%5,%6,%7}, {%8,%9}, {%0,%1,%2,%3};"
                                 : "+f"(pacc[dt][0]), "+f"(pacc[dt][1]),
                                   "+f"(pacc[dt][2]), "+f"(pacc[dt][3])
                                 : "r"(afr[0]), "r"(afr[1]), "r"(afr[2]), "r"(afr[3]),
                                   "r"(bfr[0]), "r"(bfr[1]));
                }
            }
        }
    }

    // output epilogue
    const float i0 = rinv[row], i1 = rinv[row + 8];
    const size_t r0 = (size_t)rowoff + (size_t)b * S + q0 + row;
#pragma unroll
    for (int dt = 0; dt < 2; dt++) {
        const int dim = h * 64 + warp * 16 + dt * 8 + colp;
        *(__half2*)&AS[r0 * 768 + dim]       = __floats2half2_rn(pacc[dt][0] * i0, pacc[dt][1] * i0);
        *(__half2*)&AS[(r0 + 8) * 768 + dim] = __floats2half2_rn(pacc[dt][2] * i1, pacc[dt][3] * i1);
    }
}

// ---------------- span pooling ---------------------------------------------------
__global__ __launch_bounds__(256)
void span_pool_kernel(const float* __restrict__ seq, const float* __restrict__ masks,
                      const int* __restrict__ sidx, float* __restrict__ emb, int S)
{
    const int t = blockIdx.x;
    const int b = sidx[t];
    const int tid = threadIdx.x;
    float acc0 = 0.f, acc1 = 0.f, acc2 = 0.f, msum = 0.f;
    for (int s = 0; s < S; s++) {
        const float m = masks[(size_t)t * S + s];
        msum += m;
        const float* row = seq + (size_t)(b * S + s) * 768;
        acc0 += m * row[tid];
        acc1 += m * row[tid + 256];
        acc2 += m * row[tid + 512];
    }
    const float inv = 1.f / fmaxf(msum, 1e-9f);
    emb[(size_t)t * 768 + tid]       = acc0 * inv;
    emb[(size_t)t * 768 + tid + 256] = acc1 * inv;
    emb[(size_t)t * 768 + tid + 512] = acc2 * inv;
}

// ---------------- projection head ----------------------------------------------
__global__ __launch_bounds__(256)
void proj_kernel(const float* __restrict__ emb, const float* __restrict__ pW1,
                 const float* __restrict__ pb1, const float* __restrict__ pW2,
                 const float* __restrict__ pb2, float* __restrict__ out)
{
    const int t = blockIdx.x;
    const int tid = threadIdx.x;
    __shared__ float e[768];
    __shared__ float hdn[768];
    __shared__ float o[128];
    __shared__ float red[256];
    for (int d = tid; d < 768; d += 256) e[d] = emb[(size_t)t * 768 + d];
    __syncthreads();
    for (int j = tid; j < 768; j += 256) {
        float acc = pb1[j];
        for (int d = 0; d < 768; d++) acc += e[d] * pW1[(size_t)d * 768 + j];
        hdn[j] = fmaxf(acc, 0.f);
    }
    __syncthreads();
    if (tid < 128) {
        float acc = pb2[tid];
        for (int j = 0; j < 768; j++) acc += hdn[j] * pW2[(size_t)j * 128 + tid];
        o[tid] = acc;
    }
    __syncthreads();
    red[tid] = (tid < 128) ? o[tid] * o[tid] : 0.f;
    __syncthreads();
    for (int st = 128; st > 0; st >>= 1) { if (tid < st) red[tid] += red[tid + st]; __syncthreads(); }
    const float inv = 1.f / fmaxf(sqrtf(red[0]), 1e-12f);
    if (tid < 128) out[(size_t)t * 128 + tid] = o[tid] * inv;
}

// ---------------- driver ----------------------------------------------------------
extern "C" void kernel_launch(void* const* d_in, const int* in_sizes, int n_in,
                              void* d_out, int out_size)
{
    const int*   doc_ids   = (const int*)d_in[0];
    const int*   doc_mask  = (const int*)d_in[1];
    const int*   sum_ids   = (const int*)d_in[2];
    const int*   sum_mask  = (const int*)d_in[3];
    const float* og_masks  = (const float*)d_in[4];
    const float* llm_masks = (const float*)d_in[5];
    const int*   sidx      = (const int*)d_in[6];
    const float* word_emb  = (const float*)d_in[7];
    const float* pos_emb   = (const float*)d_in[8];
    const float* tt_emb    = (const float*)d_in[9];
    const float* ln_emb_g  = (const float*)d_in[10];
    const float* ln_emb_b  = (const float*)d_in[11];
    const float* Wq = (const float*)d_in[12];
    const float* bq = (const float*)d_in[13];
    const float* Wk = (const float*)d_in[14];
    const float* bk = (const float*)d_in[15];
    const float* Wv = (const float*)d_in[16];
    const float* bv = (const float*)d_in[17];
    const float* Wo = (const float*)d_in[18];
    const float* bo = (const float*)d_in[19];
    const float* ln1_g = (const float*)d_in[20];
    const float* ln1_b = (const float*)d_in[21];
    const float* W1 = (const float*)d_in[22];
    const float* b1 = (const float*)d_in[23];
    const float* W2 = (const float*)d_in[24];
    const float* b2 = (const float*)d_in[25];
    const float* ln2_g = (const float*)d_in[26];
    const float* ln2_b = (const float*)d_in[27];
    const float* pW1 = (const float*)d_in[28];
    const float* pb1 = (const float*)d_in[29];
    const float* pW2 = (const float*)d_in[30];
    const float* pb2 = (const float*)d_in[31];
    float* out = (float*)d_out;

    float *x, *tmp, *emb, *bqkv;
    __half *qkv, *xs, *as_, *hs, *wqkv, *wo, *w1, *w2;
    cudaGetSymbolAddress((void**)&x, g_x);
    cudaGetSymbolAddress((void**)&tmp, g_t);
    cudaGetSymbolAddress((void**)&emb, g_emb);
    cudaGetSymbolAddress((void**)&bqkv, g_bqkv);
    cudaGetSymbolAddress((void**)&qkv, g_qkv);
    cudaGetSymbolAddress((void**)&xs, g_xs);
    cudaGetSymbolAddress((void**)&as_, g_as);
    cudaGetSymbolAddress((void**)&hs, g_hs);
    cudaGetSymbolAddress((void**)&wqkv, g_wqkv);
    cudaGetSymbolAddress((void**)&wo, g_wo);
    cudaGetSymbolAddress((void**)&w1, g_w1);
    cudaGetSymbolAddress((void**)&w2, g_w2);

    cudaFuncSetAttribute(gemm_fp16<0>, cudaFuncAttributeMaxDynamicSharedMemorySize, GEMM_SMEM);
    cudaFuncSetAttribute(gemm_fp16<1>, cudaFuncAttributeMaxDynamicSharedMemorySize, GEMM_SMEM);
    cudaFuncSetAttribute(gemm_fp16<2>, cudaFuncAttributeMaxDynamicSharedMemorySize, GEMM_SMEM);
    cudaFuncSetAttribute(attn_kernel, cudaFuncAttributeMaxDynamicSharedMemorySize, ATTN_SMEM);

    // one-time (per launch) weight conversion to fp16 layouts (2 launches)
    conv_qkv_kernel<<<dim3(1728, 12), 256>>>(Wq, Wk, Wv, bq, bk, bv, wqkv, bqkv);
    conv_all_kernel<<<62208, 256>>>(Wo, W1, W2, wo, w1, w2);

    // merged encoder: rows [0,4096) = doc (B=2,S=2048), rows [4096,5120) = summary
    const int T = TTOT;
    embed_ln_kernel<<<T, 192>>>(doc_ids, sum_ids, word_emb, pos_emb, tt_emb,
                                ln_emb_g, ln_emb_b, x, xs);
    for (int l = 0; l < 12; l++) {
        dim3 g768(6, T / 128), g2304(18, T / 128), g3072(24, T / 128);
        gemm_fp16<2><<<g2304, 256, GEMM_SMEM>>>(xs, wqkv + (size_t)l * 768 * 2304,
                                                bqkv + l * 2304, qkv, T, 2304, 768);
        attn_kernel<<<dim3(160, 2, 12), 128, ATTN_SMEM>>>(qkv, doc_mask, sum_mask, as_);
        gemm_fp16<0><<<g768, 256, GEMM_SMEM>>>(as_, wo + (size_t)l * 768 * 768,
                                               bo + l * 768, tmp, T, 768, 768);
        add_ln_kernel<<<T, 192>>>(x, tmp, ln1_g + l * 768, ln1_b + l * 768, xs);
        gemm_fp16<1><<<g3072, 256, GEMM_SMEM>>>(xs, w1 + (size_t)l * 768 * 3072,
                                                b1 + l * 3072, hs, T, 3072, 768);
        gemm_fp16<0><<<g768, 256, GEMM_SMEM>>>(hs, w2 + (size_t)l * 3072 * 768,
                                               b2 + l * 768, tmp, T, 768, 3072);
        add_ln_kernel<<<T, 192>>>(x, tmp, ln2_g + l * 768, ln2_b + l * 768, xs);
    }

    // span pooling + projection heads
    span_pool_kernel<<<16, 256>>>(x, og_masks, sidx, emb, 2048);
    proj_kernel<<<16, 256>>>(emb, pW1, pb1, pW2, pb2, out);
    span_pool_kernel<<<16, 256>>>(x + (size_t)4096 * 768, llm_masks, sidx, emb, 512);
    proj_kernel<<<16, 256>>>(emb, pW1, pb1, pW2, pb2, out + 16 * 128);
}